// round 12
// baseline (speedup 1.0000x reference)
#include <cuda_runtime.h>
#include <cuda_fp16.h>
#include <cstdint>

#define T_DIM 1024
#define BT 128
#define BS 64
#define KSF 68           // K f32 staging stride (words): lane banks 8*m4+g distinct
#define VSF 72           // V f32 staging stride (words): lane banks 8*g+2*m4 distinct
#define BUF_WORDS (64 * KSF + 64 * VSF)   // 8960 floats per buffer

// bit-packed mask: 8 batches x 1024 rows x 1024 bits = 1 MB
__device__ __align__(16) uint32_t g_maskbits[8u * 1024u * 32u];

__device__ __forceinline__ float ex2(float x) {
    float r; asm("ex2.approx.f32 %0, %1;" : "=f"(r) : "f"(x)); return r;
}
__device__ __forceinline__ uint32_t packh2(float lo, float hi) {
    __half2 h = __floats2half2_rn(lo, hi);   // .x = lo (low 16 bits)
    return *(uint32_t*)&h;
}
__device__ __forceinline__ void cp16(uint32_t dst, const float* src) {
    asm volatile("cp.async.cg.shared.global [%0], [%1], 16;" :: "r"(dst), "l"(src));
}

__device__ __forceinline__ void mma_f16(float d[4], const uint32_t a[4],
                                        uint32_t b0, uint32_t b1) {
    asm volatile(
        "mma.sync.aligned.m16n8k16.row.col.f32.f16.f16.f32 "
        "{%0,%1,%2,%3}, {%4,%5,%6,%7}, {%8,%9}, {%0,%1,%2,%3};\n"
        : "+f"(d[0]), "+f"(d[1]), "+f"(d[2]), "+f"(d[3])
        : "r"(a[0]), "r"(a[1]), "r"(a[2]), "r"(a[3]), "r"(b0), "r"(b1));
}

// ---------------- mask pre-pack (int32 -> bits) ----------------
__global__ void pack_mask_bits_kernel(const int* __restrict__ m) {
    uint32_t w = blockIdx.x * 256 + threadIdx.x;
    const int4* p = (const int4*)(m + (size_t)w * 32);
    uint32_t bits = 0;
    #pragma unroll
    for (int j = 0; j < 8; j++) {
        int4 v = p[j];
        bits |= (v.x != 0 ? 1u : 0u) << (4 * j + 0);
        bits |= (v.y != 0 ? 1u : 0u) << (4 * j + 1);
        bits |= (v.z != 0 ? 1u : 0u) << (4 * j + 2);
        bits |= (v.w != 0 ? 1u : 0u) << (4 * j + 3);
    }
    g_maskbits[w] = bits;
}

__global__ __launch_bounds__(128, 2) void attn_flash_kernel(
    const float* __restrict__ qkv,
    const float* __restrict__ qk_bias,
    float* __restrict__ out)
{
    extern __shared__ __align__(16) float dyns[];   // 3 x BUF_WORDS f32

    const int tid = threadIdx.x;
    const int lane = tid & 31;
    const int g = lane >> 2;
    const int m4 = lane & 3;

    const int tile_t = blockIdx.x;   // 0..7
    const int bh = blockIdx.y;       // 0..127

    const float* qp = qkv + (size_t)bh * 192 * T_DIM;
    const float* kp = qp + 64 * T_DIM;
    const float* vp = qp + 128 * T_DIM;
    const uint32_t* mb = g_maskbits + (size_t)(bh & 7) * 1024u * 32u;

    const int t0 = tile_t * BT + (tid >> 5) * 32;
    const float bias2 = qk_bias[0] * 1.4426950408889634f;
    const float scale2 = 0.125f * 1.4426950408889634f;

    // mask row bases (fixed across stages)
    const uint32_t* mrow0l = mb + (size_t)(t0 + g) * 32;
    const uint32_t* mrow0h = mb + (size_t)(t0 + g + 8) * 32;
    const uint32_t* mrow1l = mb + (size_t)(t0 + 16 + g) * 32;
    const uint32_t* mrow1h = mb + (size_t)(t0 + 24 + g) * 32;

    // ---- Q fragments (fp16 m16n8k16 A layout), loaded once ----
    uint32_t qf[2][4][4];
    #pragma unroll
    for (int r = 0; r < 2; r++) {
        const int t = t0 + 16 * r + g;
        #pragma unroll
        for (int k4 = 0; k4 < 4; k4++) {
            const int c0 = 16 * k4 + 2 * m4;
            qf[r][k4][0] = packh2(qp[(size_t)c0 * T_DIM + t],           qp[(size_t)(c0 + 1) * T_DIM + t]);
            qf[r][k4][1] = packh2(qp[(size_t)c0 * T_DIM + t + 8],       qp[(size_t)(c0 + 1) * T_DIM + t + 8]);
            qf[r][k4][2] = packh2(qp[(size_t)(c0 + 8) * T_DIM + t],     qp[(size_t)(c0 + 9) * T_DIM + t]);
            qf[r][k4][3] = packh2(qp[(size_t)(c0 + 8) * T_DIM + t + 8], qp[(size_t)(c0 + 9) * T_DIM + t + 8]);
        }
    }

    float o[2][8][4];
    #pragma unroll
    for (int r = 0; r < 2; r++)
        #pragma unroll
        for (int n = 0; n < 8; n++)
            { o[r][n][0]=0.f; o[r][n][1]=0.f; o[r][n][2]=0.f; o[r][n][3]=0.f; }
    float lr[2]  = {0.f, 0.f};
    float lrh[2] = {0.f, 0.f};

    float sacc[2][8][4];       // S accumulators (stage st+1)
    uint32_t pk[2][8][2];      // packed P fp16 pairs (stage st)

    const uint32_t smem_base = (uint32_t)__cvta_generic_to_shared(dyns);
    const int crow = tid >> 4;          // staging row base
    const int cj = tid & 15;            // 16B chunk in row

    // ---- staging issuer (K and V f32 tiles for stage stg -> buf stg%3) ----
    auto issue_stage = [&](int stg) {
        const int s1 = stg * BS;
        const uint32_t base = smem_base + (uint32_t)((stg % 3) * BUF_WORDS) * 4;
        const uint32_t kb = base;
        const uint32_t vb = base + 64 * KSF * 4;
        #pragma unroll
        for (int it = 0; it < 8; it++) {
            int c = crow + it * 8;
            cp16(kb + (uint32_t)(c * KSF + cj * 4) * 4, kp + (size_t)c * T_DIM + s1 + cj * 4);
            cp16(vb + (uint32_t)(c * VSF + cj * 4) * 4, vp + (size_t)c * T_DIM + s1 + cj * 4);
        }
        asm volatile("cp.async.commit_group;" ::: "memory");
    };

    // ---- S = Q^T K (inline f32->f16 pack) ----
    auto qk_only = [&](const float* Kf) {
        #pragma unroll
        for (int r = 0; r < 2; r++)
            #pragma unroll
            for (int n = 0; n < 8; n++)
                { sacc[r][n][0]=0.f; sacc[r][n][1]=0.f; sacc[r][n][2]=0.f; sacc[r][n][3]=0.f; }
        #pragma unroll
        for (int k4 = 0; k4 < 4; k4++) {
            const float* kr0 = Kf + (16 * k4 + 2 * m4) * KSF;
            const float* kr1 = kr0 + KSF;
            const float* kr2 = kr0 + 8 * KSF;
            const float* kr3 = kr0 + 9 * KSF;
            #pragma unroll
            for (int n = 0; n < 8; n++) {
                const int s = 8 * n + g;
                uint32_t b0 = packh2(kr0[s], kr1[s]);
                uint32_t b1 = packh2(kr2[s], kr3[s]);
                mma_f16(sacc[0][n], qf[0][k4], b0, b1);
                mma_f16(sacc[1][n], qf[1][k4], b0, b1);
            }
        }
    };

    // ---- O += P V^T for one k4 slice (A from pk) ----
    auto pv_slice = [&](const float* Vf, int k4) {
        uint32_t a0[4] = { pk[0][2*k4][0], pk[0][2*k4][1], pk[0][2*k4+1][0], pk[0][2*k4+1][1] };
        uint32_t a1[4] = { pk[1][2*k4][0], pk[1][2*k4][1], pk[1][2*k4+1][0], pk[1][2*k4+1][1] };
        #pragma unroll
        for (int n = 0; n < 8; n++) {
            const float* vr = Vf + (8 * n + g) * VSF + 16 * k4 + 2 * m4;
            float2 v0 = *(const float2*)vr;
            float2 v1 = *(const float2*)(vr + 8);
            uint32_t b0 = packh2(v0.x, v0.y);
            uint32_t b1 = packh2(v1.x, v1.y);
            mma_f16(o[0][n], a0, b0, b1);
            mma_f16(o[1][n], a1, b0, b1);
        }
    };

    // ---- interleaved: QK(st+1) k4-slice + PV(st) k4-slice (independent chains) ----
    auto qk_pv = [&](const float* Kn, const float* Vc) {
        #pragma unroll
        for (int r = 0; r < 2; r++)
            #pragma unroll
            for (int n = 0; n < 8; n++)
                { sacc[r][n][0]=0.f; sacc[r][n][1]=0.f; sacc[r][n][2]=0.f; sacc[r][n][3]=0.f; }
        #pragma unroll
        for (int k4 = 0; k4 < 4; k4++) {
            const float* kr0 = Kn + (16 * k4 + 2 * m4) * KSF;
            const float* kr1 = kr0 + KSF;
            const float* kr2 = kr0 + 8 * KSF;
            const float* kr3 = kr0 + 9 * KSF;
            #pragma unroll
            for (int n = 0; n < 8; n++) {
                const int s = 8 * n + g;
                uint32_t b0 = packh2(kr0[s], kr1[s]);
                uint32_t b1 = packh2(kr2[s], kr3[s]);
                mma_f16(sacc[0][n], qf[0][k4], b0, b1);
                mma_f16(sacc[1][n], qf[1][k4], b0, b1);
            }
            pv_slice(Vc, k4);
        }
    };

    // ---- softmax: sacc -> pk (packed fp16 pairs) + row-sum partials ----
    auto softmax_pack = [&](int stg) {
        uint2 m0l = *(const uint2*)(mrow0l + stg * 2);
        uint2 m0h = *(const uint2*)(mrow0h + stg * 2);
        uint2 m1l = *(const uint2*)(mrow1l + stg * 2);
        uint2 m1h = *(const uint2*)(mrow1h + stg * 2);
        #pragma unroll
        for (int r = 0; r < 2; r++) {
            uint2 ml = (r == 0) ? m0l : m1l;
            uint2 mh = (r == 0) ? m0h : m1h;
            uint32_t lx = ml.x >> (2 * m4), ly = ml.y >> (2 * m4);
            uint32_t hx = mh.x >> (2 * m4), hy = mh.y >> (2 * m4);
            #pragma unroll
            for (int n = 0; n < 8; n++) {
                uint32_t wl = ((n < 4) ? lx : ly) >> (8 * (n & 3));
                uint32_t wh = ((n < 4) ? hx : hy) >> (8 * (n & 3));
                float e00 = ex2(fmaf(sacc[r][n][0], scale2, bias2));
                float e01 = ex2(fmaf(sacc[r][n][1], scale2, bias2));
                float e10 = ex2(fmaf(sacc[r][n][2], scale2, bias2));
                float e11 = ex2(fmaf(sacc[r][n][3], scale2, bias2));
                float p00 = (wl & 1u) ? e00 : 0.f;
                float p01 = (wl & 2u) ? e01 : 0.f;
                float p10 = (wh & 1u) ? e10 : 0.f;
                float p11 = (wh & 2u) ? e11 : 0.f;
                pk[r][n][0] = packh2(p00, p01);
                pk[r][n][1] = packh2(p10, p11);
                lr[r]  += p00 + p01;
                lrh[r] += p10 + p11;
            }
        }
    };

    // ================= pipeline =================
    issue_stage(0);
    issue_stage(1);
    asm volatile("cp.async.wait_group 1;" ::: "memory");   // stage 0 landed
    __syncthreads();
    qk_only(dyns + 0 * BUF_WORDS);
    softmax_pack(0);

    for (int st = 0; st < 15; st++) {
        asm volatile("cp.async.wait_group 0;" ::: "memory");  // stage st+1 landed
        __syncthreads();   // + all warps done with PV(st-1) reads of buf (st-1)%3
        if (st < 14) issue_stage(st + 2);   // overwrites buf (st-1)%3

        const float* Kn = dyns + ((st + 1) % 3) * BUF_WORDS;
        const float* Vc = dyns + (st % 3) * BUF_WORDS + 64 * KSF;
        qk_pv(Kn, Vc);          // PV(st) || QK(st+1)
        softmax_pack(st + 1);
    }

    // epilogue: PV(15) from buf 15%3 = 0
    {
        const float* Vc = dyns + 0 * BUF_WORDS + 64 * KSF;
        #pragma unroll
        for (int k4 = 0; k4 < 4; k4++) pv_slice(Vc, k4);
    }

    // ---- deferred row-sum reduction ----
    #pragma unroll
    for (int r = 0; r < 2; r++) {
        lr[r]  += __shfl_xor_sync(0xffffffffu, lr[r], 1);
        lr[r]  += __shfl_xor_sync(0xffffffffu, lr[r], 2);
        lrh[r] += __shfl_xor_sync(0xffffffffu, lrh[r], 1);
        lrh[r] += __shfl_xor_sync(0xffffffffu, lrh[r], 2);
    }

    float* ob = out + (size_t)bh * 64 * T_DIM;
    #pragma unroll
    for (int r = 0; r < 2; r++) {
        float il0 = 1.f / lr[r];
        float il1 = 1.f / lrh[r];
        #pragma unroll
        for (int n = 0; n < 8; n++) {
            int c = 8 * n + 2 * m4;
            int t = t0 + 16 * r + g;
            ob[(size_t)c       * T_DIM + t]     = o[r][n][0] * il0;
            ob[(size_t)(c + 1) * T_DIM + t]     = o[r][n][1] * il0;
            ob[(size_t)c       * T_DIM + t + 8] = o[r][n][2] * il1;
            ob[(size_t)(c + 1) * T_DIM + t + 8] = o[r][n][3] * il1;
        }
    }
}

extern "C" void kernel_launch(void* const* d_in, const int* in_sizes, int n_in,
                              void* d_out, int out_size) {
    const float* qkv = (const float*)d_in[0];
    const int* mask = (const int*)d_in[1];
    const float* bias = (const float*)d_in[2];
    float* out = (float*)d_out;

    pack_mask_bits_kernel<<<1024, 256>>>(mask);

    const int dyn_smem = 3 * BUF_WORDS * 4;   // 107,520 B
    static int attr_set = 0;
    if (!attr_set) {
        cudaFuncSetAttribute(attn_flash_kernel,
                             cudaFuncAttributeMaxDynamicSharedMemorySize, dyn_smem);
        attr_set = 1;
    }
    dim3 grid(T_DIM / BT, 8 * 16);
    attn_flash_kernel<<<grid, 128, dyn_smem>>>(qkv, bias, out);
}

// round 13
// speedup vs baseline: 1.3576x; 1.3576x over previous
#include <cuda_runtime.h>
#include <cuda_fp16.h>
#include <cstdint>

#define T_DIM 1024
#define BT 128
#define BS 64
#define KSF 68           // K f32 staging stride (words)
#define VSF 72           // V f32 staging stride (words)
#define BUF_WORDS (64 * KSF + 64 * VSF)   // 8960 floats per buffer

// bit-packed mask: 8 batches x 1024 rows x 1024 bits = 1 MB
__device__ __align__(16) uint32_t g_maskbits[8u * 1024u * 32u];

__device__ __forceinline__ float ex2(float x) {
    float r; asm("ex2.approx.f32 %0, %1;" : "=f"(r) : "f"(x)); return r;
}
__device__ __forceinline__ uint32_t packh2(float lo, float hi) {
    __half2 h = __floats2half2_rn(lo, hi);   // .x = lo (low 16 bits)
    return *(uint32_t*)&h;
}
__device__ __forceinline__ void cp16(uint32_t dst, const float* src) {
    asm volatile("cp.async.cg.shared.global [%0], [%1], 16;" :: "r"(dst), "l"(src));
}

__device__ __forceinline__ void mma_f16(float d[4], const uint32_t a[4],
                                        uint32_t b0, uint32_t b1) {
    asm volatile(
        "mma.sync.aligned.m16n8k16.row.col.f32.f16.f16.f32 "
        "{%0,%1,%2,%3}, {%4,%5,%6,%7}, {%8,%9}, {%0,%1,%2,%3};\n"
        : "+f"(d[0]), "+f"(d[1]), "+f"(d[2]), "+f"(d[3])
        : "r"(a[0]), "r"(a[1]), "r"(a[2]), "r"(a[3]), "r"(b0), "r"(b1));
}

// ---------------- mask pre-pack (int32 -> bits) ----------------
__global__ void pack_mask_bits_kernel(const int* __restrict__ m) {
    uint32_t w = blockIdx.x * 256 + threadIdx.x;
    const int4* p = (const int4*)(m + (size_t)w * 32);
    uint32_t bits = 0;
    #pragma unroll
    for (int j = 0; j < 8; j++) {
        int4 v = p[j];
        bits |= (v.x != 0 ? 1u : 0u) << (4 * j + 0);
        bits |= (v.y != 0 ? 1u : 0u) << (4 * j + 1);
        bits |= (v.z != 0 ? 1u : 0u) << (4 * j + 2);
        bits |= (v.w != 0 ? 1u : 0u) << (4 * j + 3);
    }
    g_maskbits[w] = bits;
}

__global__ __launch_bounds__(128, 3) void attn_flash_kernel(
    const float* __restrict__ qkv,
    const float* __restrict__ qk_bias,
    float* __restrict__ out)
{
    extern __shared__ __align__(16) float dyns[];   // 2 x BUF_WORDS f32

    const int tid = threadIdx.x;
    const int lane = tid & 31;
    const int g = lane >> 2;
    const int m4 = lane & 3;

    const int tile_t = blockIdx.x;   // 0..7
    const int bh = blockIdx.y;       // 0..127

    const float* qp = qkv + (size_t)bh * 192 * T_DIM;
    const float* kp = qp + 64 * T_DIM;
    const float* vp = qp + 128 * T_DIM;
    const uint32_t* mb = g_maskbits + (size_t)(bh & 7) * 1024u * 32u;

    const int t0 = tile_t * BT + (tid >> 5) * 32;
    const float bias2 = qk_bias[0] * 1.4426950408889634f;
    const float scale2 = 0.125f * 1.4426950408889634f;

    // mask row bases (fixed across stages)
    const uint32_t* mrow0l = mb + (size_t)(t0 + g) * 32;
    const uint32_t* mrow0h = mb + (size_t)(t0 + g + 8) * 32;
    const uint32_t* mrow1l = mb + (size_t)(t0 + 16 + g) * 32;
    const uint32_t* mrow1h = mb + (size_t)(t0 + 24 + g) * 32;

    // ---- Q fragments (fp16 m16n8k16 A layout), loaded once ----
    uint32_t qf[2][4][4];
    #pragma unroll
    for (int r = 0; r < 2; r++) {
        const int t = t0 + 16 * r + g;
        #pragma unroll
        for (int k4 = 0; k4 < 4; k4++) {
            const int c0 = 16 * k4 + 2 * m4;
            qf[r][k4][0] = packh2(qp[(size_t)c0 * T_DIM + t],           qp[(size_t)(c0 + 1) * T_DIM + t]);
            qf[r][k4][1] = packh2(qp[(size_t)c0 * T_DIM + t + 8],       qp[(size_t)(c0 + 1) * T_DIM + t + 8]);
            qf[r][k4][2] = packh2(qp[(size_t)(c0 + 8) * T_DIM + t],     qp[(size_t)(c0 + 9) * T_DIM + t]);
            qf[r][k4][3] = packh2(qp[(size_t)(c0 + 8) * T_DIM + t + 8], qp[(size_t)(c0 + 9) * T_DIM + t + 8]);
        }
    }

    float o[2][8][4];
    #pragma unroll
    for (int r = 0; r < 2; r++)
        #pragma unroll
        for (int n = 0; n < 8; n++)
            { o[r][n][0]=0.f; o[r][n][1]=0.f; o[r][n][2]=0.f; o[r][n][3]=0.f; }
    float lr[2]  = {0.f, 0.f};
    float lrh[2] = {0.f, 0.f};

    const uint32_t smem_base = (uint32_t)__cvta_generic_to_shared(dyns);
    const int crow = tid >> 4;
    const int cj = tid & 15;

    // ---- prologue: stage 0 f32 loads into buffer 0 ----
    {
        const uint32_t kb = smem_base;
        const uint32_t vb = smem_base + 64 * KSF * 4;
        #pragma unroll
        for (int it = 0; it < 8; it++) {
            int c = crow + it * 8;
            cp16(kb + (uint32_t)(c * KSF + cj * 4) * 4, kp + (size_t)c * T_DIM + cj * 4);
            cp16(vb + (uint32_t)(c * VSF + cj * 4) * 4, vp + (size_t)c * T_DIM + cj * 4);
        }
        asm volatile("cp.async.commit_group;" ::: "memory");
    }

    for (int st = 0; st < 16; st++) {
        asm volatile("cp.async.wait_group 0;" ::: "memory");
        __syncthreads();   // buf(st) ready; reads of buf(st-1) complete

        if (st < 15) {
            const int s1 = (st + 1) * BS;
            const uint32_t base1 = smem_base + (uint32_t)(((st + 1) & 1) * BUF_WORDS) * 4;
            const uint32_t kb = base1;
            const uint32_t vb = base1 + 64 * KSF * 4;
            #pragma unroll
            for (int it = 0; it < 8; it++) {
                int c = crow + it * 8;
                cp16(kb + (uint32_t)(c * KSF + cj * 4) * 4, kp + (size_t)c * T_DIM + s1 + cj * 4);
                cp16(vb + (uint32_t)(c * VSF + cj * 4) * 4, vp + (size_t)c * T_DIM + s1 + cj * 4);
            }
            asm volatile("cp.async.commit_group;" ::: "memory");
        }

        const float* Kf = dyns + (st & 1) * BUF_WORDS;
        const float* Vf = Kf + 64 * KSF;
        // hoisted reg bases; all fragment LDS become [base + compile-time imm]
        const float* Kbase = Kf + 2 * m4 * KSF + g;          // + imm(16*k4*KSF + 8*n)
        const float* Vbase = Vf + g * VSF + 2 * m4;          // + imm(8*n*VSF + 16*k4)

        // ---- stage mask bits ----
        uint2 m0l = *(const uint2*)(mrow0l + st * 2);
        uint2 m0h = *(const uint2*)(mrow0h + st * 2);
        uint2 m1l = *(const uint2*)(mrow1l + st * 2);
        uint2 m1h = *(const uint2*)(mrow1h + st * 2);

        // ==== 4 groups: {QK(2nb), softmax; QK(2nb+1), softmax; PV slice nb} ====
        #pragma unroll
        for (int nb = 0; nb < 4; nb++) {
            uint32_t pknb[2][2][2];   // [r][j][half] packed P for n = 2nb+j

            #pragma unroll
            for (int j = 0; j < 2; j++) {
                const int n = 2 * nb + j;

                float sc[2][4] = {{0.f,0.f,0.f,0.f},{0.f,0.f,0.f,0.f}};
                #pragma unroll
                for (int k4 = 0; k4 < 4; k4++) {
                    const float* ka = Kbase + 16 * k4 * KSF + 8 * n;
                    uint32_t b0 = packh2(ka[0],       ka[KSF]);
                    uint32_t b1 = packh2(ka[8 * KSF], ka[9 * KSF]);
                    mma_f16(sc[0], qf[0][k4], b0, b1);
                    mma_f16(sc[1], qf[1][k4], b0, b1);
                }

                // softmax for this n-block
                #pragma unroll
                for (int r = 0; r < 2; r++) {
                    uint32_t mlw = (r == 0) ? ((n < 4) ? m0l.x : m0l.y) : ((n < 4) ? m1l.x : m1l.y);
                    uint32_t mhw = (r == 0) ? ((n < 4) ? m0h.x : m0h.y) : ((n < 4) ? m1h.x : m1h.y);
                    uint32_t wl = mlw >> (2 * m4 + 8 * (n & 3));
                    uint32_t wh = mhw >> (2 * m4 + 8 * (n & 3));
                    float e00 = ex2(fmaf(sc[r][0], scale2, bias2));
                    float e01 = ex2(fmaf(sc[r][1], scale2, bias2));
                    float e10 = ex2(fmaf(sc[r][2], scale2, bias2));
                    float e11 = ex2(fmaf(sc[r][3], scale2, bias2));
                    float p00 = (wl & 1u) ? e00 : 0.f;
                    float p01 = (wl & 2u) ? e01 : 0.f;
                    float p10 = (wh & 1u) ? e10 : 0.f;
                    float p11 = (wh & 2u) ? e11 : 0.f;
                    pknb[r][j][0] = packh2(p00, p01);
                    pknb[r][j][1] = packh2(p10, p11);
                    if (r == 0) { lr[0]  += p00 + p01; lrh[0] += p10 + p11; }
                    else        { lr[1]  += p00 + p01; lrh[1] += p10 + p11; }
                }
            }

            // PV slice k4 = nb (consumes exactly n-blocks 2nb, 2nb+1)
            uint32_t a0[4] = { pknb[0][0][0], pknb[0][0][1], pknb[0][1][0], pknb[0][1][1] };
            uint32_t a1[4] = { pknb[1][0][0], pknb[1][0][1], pknb[1][1][0], pknb[1][1][1] };
            #pragma unroll
            for (int n = 0; n < 8; n++) {
                const float* va = Vbase + 8 * n * VSF + 16 * nb;
                float2 v0 = *(const float2*)va;
                float2 v1 = *(const float2*)(va + 8);
                uint32_t b0 = packh2(v0.x, v0.y);
                uint32_t b1 = packh2(v1.x, v1.y);
                mma_f16(o[0][n], a0, b0, b1);
                mma_f16(o[1][n], a1, b0, b1);
            }
        }
    }

    // ---- deferred row-sum reduction ----
    #pragma unroll
    for (int r = 0; r < 2; r++) {
        lr[r]  += __shfl_xor_sync(0xffffffffu, lr[r], 1);
        lr[r]  += __shfl_xor_sync(0xffffffffu, lr[r], 2);
        lrh[r] += __shfl_xor_sync(0xffffffffu, lrh[r], 1);
        lrh[r] += __shfl_xor_sync(0xffffffffu, lrh[r], 2);
    }

    float* ob = out + (size_t)bh * 64 * T_DIM;
    #pragma unroll
    for (int r = 0; r < 2; r++) {
        float il0 = 1.f / lr[r];
        float il1 = 1.f / lrh[r];
        #pragma unroll
        for (int n = 0; n < 8; n++) {
            int c = 8 * n + 2 * m4;
            int t = t0 + 16 * r + g;
            ob[(size_t)c       * T_DIM + t]     = o[r][n][0] * il0;
            ob[(size_t)(c + 1) * T_DIM + t]     = o[r][n][1] * il0;
            ob[(size_t)c       * T_DIM + t + 8] = o[r][n][2] * il1;
            ob[(size_t)(c + 1) * T_DIM + t + 8] = o[r][n][3] * il1;
        }
    }
}

extern "C" void kernel_launch(void* const* d_in, const int* in_sizes, int n_in,
                              void* d_out, int out_size) {
    const float* qkv = (const float*)d_in[0];
    const int* mask = (const int*)d_in[1];
    const float* bias = (const float*)d_in[2];
    float* out = (float*)d_out;

    pack_mask_bits_kernel<<<1024, 256>>>(mask);

    const int dyn_smem = 2 * BUF_WORDS * 4;   // 71,680 B per CTA
    static int attr_set = 0;
    if (!attr_set) {
        cudaFuncSetAttribute(attn_flash_kernel,
                             cudaFuncAttributeMaxDynamicSharedMemorySize, dyn_smem);
        attr_set = 1;
    }
    dim3 grid(T_DIM / BT, 8 * 16);
    attn_flash_kernel<<<grid, 128, dyn_smem>>>(qkv, bias, out);
}

// round 14
// speedup vs baseline: 1.3578x; 1.0002x over previous
#include <cuda_runtime.h>
#include <cuda_fp16.h>
#include <cstdint>

#define T_DIM 1024
#define BT 128
#define BS 64
#define KSF 68           // K f32 staging stride (words)
#define VSF 72           // V f32 staging stride (words)
#define BUF_WORDS (64 * KSF + 64 * VSF)   // 8960 floats per buffer

// bit-packed mask: 8 batches x 1024 rows x 1024 bits = 1 MB
__device__ __align__(16) uint32_t g_maskbits[8u * 1024u * 32u];

__device__ __forceinline__ float ex2(float x) {
    float r; asm("ex2.approx.f32 %0, %1;" : "=f"(r) : "f"(x)); return r;
}
__device__ __forceinline__ uint32_t packh2(float lo, float hi) {
    __half2 h = __floats2half2_rn(lo, hi);   // .x = lo (low 16 bits)
    return *(uint32_t*)&h;
}
__device__ __forceinline__ void cp16(uint32_t dst, const float* src) {
    asm volatile("cp.async.cg.shared.global [%0], [%1], 16;" :: "r"(dst), "l"(src));
}

__device__ __forceinline__ void mma_f16(float d[4], const uint32_t a[4],
                                        uint32_t b0, uint32_t b1) {
    asm volatile(
        "mma.sync.aligned.m16n8k16.row.col.f32.f16.f16.f32 "
        "{%0,%1,%2,%3}, {%4,%5,%6,%7}, {%8,%9}, {%0,%1,%2,%3};\n"
        : "+f"(d[0]), "+f"(d[1]), "+f"(d[2]), "+f"(d[3])
        : "r"(a[0]), "r"(a[1]), "r"(a[2]), "r"(a[3]), "r"(b0), "r"(b1));
}

// ---------------- mask pre-pack (int32 -> bits) ----------------
__global__ void pack_mask_bits_kernel(const int* __restrict__ m) {
    uint32_t w = blockIdx.x * 256 + threadIdx.x;
    const int4* p = (const int4*)(m + (size_t)w * 32);
    uint32_t bits = 0;
    #pragma unroll
    for (int j = 0; j < 8; j++) {
        int4 v = p[j];
        bits |= (v.x != 0 ? 1u : 0u) << (4 * j + 0);
        bits |= (v.y != 0 ? 1u : 0u) << (4 * j + 1);
        bits |= (v.z != 0 ? 1u : 0u) << (4 * j + 2);
        bits |= (v.w != 0 ? 1u : 0u) << (4 * j + 3);
    }
    g_maskbits[w] = bits;
}

__global__ __launch_bounds__(128, 3) void attn_flash_kernel(
    const float* __restrict__ qkv,
    const float* __restrict__ qk_bias,
    float* __restrict__ out)
{
    extern __shared__ __align__(16) float dyns[];   // 2 x BUF_WORDS f32

    const int tid = threadIdx.x;
    const int lane = tid & 31;
    const int g = lane >> 2;
    const int m4 = lane & 3;

    const int tile_t = blockIdx.x;   // 0..7
    const int bh = blockIdx.y;       // 0..127

    const float* qp = qkv + (size_t)bh * 192 * T_DIM;
    const float* kp = qp + 64 * T_DIM;
    const float* vp = qp + 128 * T_DIM;
    const uint32_t* mb = g_maskbits + (size_t)(bh & 7) * 1024u * 32u;

    const int t0 = tile_t * BT + (tid >> 5) * 32;
    const float bias2 = qk_bias[0] * 1.4426950408889634f;
    const float scale2 = 0.125f * 1.4426950408889634f;

    // mask row bases (fixed across stages)
    const uint32_t* mrow0l = mb + (size_t)(t0 + g) * 32;
    const uint32_t* mrow0h = mb + (size_t)(t0 + g + 8) * 32;
    const uint32_t* mrow1l = mb + (size_t)(t0 + 16 + g) * 32;
    const uint32_t* mrow1h = mb + (size_t)(t0 + 24 + g) * 32;

    // ---- Q fragments (fp16 m16n8k16 A layout), loaded once ----
    uint32_t qf[2][4][4];
    #pragma unroll
    for (int r = 0; r < 2; r++) {
        const int t = t0 + 16 * r + g;
        #pragma unroll
        for (int k4 = 0; k4 < 4; k4++) {
            const int c0 = 16 * k4 + 2 * m4;
            qf[r][k4][0] = packh2(qp[(size_t)c0 * T_DIM + t],           qp[(size_t)(c0 + 1) * T_DIM + t]);
            qf[r][k4][1] = packh2(qp[(size_t)c0 * T_DIM + t + 8],       qp[(size_t)(c0 + 1) * T_DIM + t + 8]);
            qf[r][k4][2] = packh2(qp[(size_t)(c0 + 8) * T_DIM + t],     qp[(size_t)(c0 + 9) * T_DIM + t]);
            qf[r][k4][3] = packh2(qp[(size_t)(c0 + 8) * T_DIM + t + 8], qp[(size_t)(c0 + 9) * T_DIM + t + 8]);
        }
    }

    float o[2][8][4];
    #pragma unroll
    for (int r = 0; r < 2; r++)
        #pragma unroll
        for (int n = 0; n < 8; n++)
            { o[r][n][0]=0.f; o[r][n][1]=0.f; o[r][n][2]=0.f; o[r][n][3]=0.f; }
    float lr[2]  = {0.f, 0.f};
    float lrh[2] = {0.f, 0.f};

    const uint32_t smem_base = (uint32_t)__cvta_generic_to_shared(dyns);
    const int crow = tid >> 4;
    const int cj = tid & 15;

    // ---- prologue: stage 0 f32 loads into buffer 0 ----
    {
        const uint32_t kb = smem_base;
        const uint32_t vb = smem_base + 64 * KSF * 4;
        #pragma unroll
        for (int it = 0; it < 8; it++) {
            int c = crow + it * 8;
            cp16(kb + (uint32_t)(c * KSF + cj * 4) * 4, kp + (size_t)c * T_DIM + cj * 4);
            cp16(vb + (uint32_t)(c * VSF + cj * 4) * 4, vp + (size_t)c * T_DIM + cj * 4);
        }
        asm volatile("cp.async.commit_group;" ::: "memory");
    }

    for (int st = 0; st < 16; st++) {
        asm volatile("cp.async.wait_group 0;" ::: "memory");
        __syncthreads();   // buf(st) ready; reads of buf(st-1) complete

        if (st < 15) {
            const int s1 = (st + 1) * BS;
            const uint32_t base1 = smem_base + (uint32_t)(((st + 1) & 1) * BUF_WORDS) * 4;
            const uint32_t kb = base1;
            const uint32_t vb = base1 + 64 * KSF * 4;
            #pragma unroll
            for (int it = 0; it < 8; it++) {
                int c = crow + it * 8;
                cp16(kb + (uint32_t)(c * KSF + cj * 4) * 4, kp + (size_t)c * T_DIM + s1 + cj * 4);
                cp16(vb + (uint32_t)(c * VSF + cj * 4) * 4, vp + (size_t)c * T_DIM + s1 + cj * 4);
            }
            asm volatile("cp.async.commit_group;" ::: "memory");
        }

        const float* Kf = dyns + (st & 1) * BUF_WORDS;
        const float* Vf = Kf + 64 * KSF;
        // hoisted reg bases; all fragment LDS become [base + compile-time imm]
        const float* Kbase = Kf + 2 * m4 * KSF + g;          // + imm(16*k4*KSF + 8*n)
        const float* Vbase = Vf + g * VSF + 2 * m4;          // + imm(8*n*VSF + 16*k4)

        // ---- stage mask bits ----
        uint2 m0l = *(const uint2*)(mrow0l + st * 2);
        uint2 m0h = *(const uint2*)(mrow0h + st * 2);
        uint2 m1l = *(const uint2*)(mrow1l + st * 2);
        uint2 m1h = *(const uint2*)(mrow1h + st * 2);

        // ==== 4 groups: {QK(2nb), softmax; QK(2nb+1), softmax; PV slice nb} ====
        #pragma unroll
        for (int nb = 0; nb < 4; nb++) {
            uint32_t pknb[2][2][2];   // [r][j][half] packed P for n = 2nb+j

            #pragma unroll
            for (int j = 0; j < 2; j++) {
                const int n = 2 * nb + j;

                float sc[2][4] = {{0.f,0.f,0.f,0.f},{0.f,0.f,0.f,0.f}};
                #pragma unroll
                for (int k4 = 0; k4 < 4; k4++) {
                    const float* ka = Kbase + 16 * k4 * KSF + 8 * n;
                    uint32_t b0 = packh2(ka[0],       ka[KSF]);
                    uint32_t b1 = packh2(ka[8 * KSF], ka[9 * KSF]);
                    mma_f16(sc[0], qf[0][k4], b0, b1);
                    mma_f16(sc[1], qf[1][k4], b0, b1);
                }

                // softmax for this n-block
                #pragma unroll
                for (int r = 0; r < 2; r++) {
                    uint32_t mlw = (r == 0) ? ((n < 4) ? m0l.x : m0l.y) : ((n < 4) ? m1l.x : m1l.y);
                    uint32_t mhw = (r == 0) ? ((n < 4) ? m0h.x : m0h.y) : ((n < 4) ? m1h.x : m1h.y);
                    uint32_t wl = mlw >> (2 * m4 + 8 * (n & 3));
                    uint32_t wh = mhw >> (2 * m4 + 8 * (n & 3));
                    float e00 = ex2(fmaf(sc[r][0], scale2, bias2));
                    float e01 = ex2(fmaf(sc[r][1], scale2, bias2));
                    float e10 = ex2(fmaf(sc[r][2], scale2, bias2));
                    float e11 = ex2(fmaf(sc[r][3], scale2, bias2));
                    float p00 = (wl & 1u) ? e00 : 0.f;
                    float p01 = (wl & 2u) ? e01 : 0.f;
                    float p10 = (wh & 1u) ? e10 : 0.f;
                    float p11 = (wh & 2u) ? e11 : 0.f;
                    pknb[r][j][0] = packh2(p00, p01);
                    pknb[r][j][1] = packh2(p10, p11);
                    if (r == 0) { lr[0]  += p00 + p01; lrh[0] += p10 + p11; }
                    else        { lr[1]  += p00 + p01; lrh[1] += p10 + p11; }
                }
            }

            // PV slice k4 = nb (consumes exactly n-blocks 2nb, 2nb+1)
            uint32_t a0[4] = { pknb[0][0][0], pknb[0][0][1], pknb[0][1][0], pknb[0][1][1] };
            uint32_t a1[4] = { pknb[1][0][0], pknb[1][0][1], pknb[1][1][0], pknb[1][1][1] };
            #pragma unroll
            for (int n = 0; n < 8; n++) {
                const float* va = Vbase + 8 * n * VSF + 16 * nb;
                float2 v0 = *(const float2*)va;
                float2 v1 = *(const float2*)(va + 8);
                uint32_t b0 = packh2(v0.x, v0.y);
                uint32_t b1 = packh2(v1.x, v1.y);
                mma_f16(o[0][n], a0, b0, b1);
                mma_f16(o[1][n], a1, b0, b1);
            }
        }
    }

    // ---- deferred row-sum reduction ----
    #pragma unroll
    for (int r = 0; r < 2; r++) {
        lr[r]  += __shfl_xor_sync(0xffffffffu, lr[r], 1);
        lr[r]  += __shfl_xor_sync(0xffffffffu, lr[r], 2);
        lrh[r] += __shfl_xor_sync(0xffffffffu, lrh[r], 1);
        lrh[r] += __shfl_xor_sync(0xffffffffu, lrh[r], 2);
    }

    float* ob = out + (size_t)bh * 64 * T_DIM;
    #pragma unroll
    for (int r = 0; r < 2; r++) {
        float il0 = 1.f / lr[r];
        float il1 = 1.f / lrh[r];
        #pragma unroll
        for (int n = 0; n < 8; n++) {
            int c = 8 * n + 2 * m4;
            int t = t0 + 16 * r + g;
            ob[(size_t)c       * T_DIM + t]     = o[r][n][0] * il0;
            ob[(size_t)(c + 1) * T_DIM + t]     = o[r][n][1] * il0;
            ob[(size_t)c       * T_DIM + t + 8] = o[r][n][2] * il1;
            ob[(size_t)(c + 1) * T_DIM + t + 8] = o[r][n][3] * il1;
        }
    }
}

extern "C" void kernel_launch(void* const* d_in, const int* in_sizes, int n_in,
                              void* d_out, int out_size) {
    const float* qkv = (const float*)d_in[0];
    const int* mask = (const int*)d_in[1];
    const float* bias = (const float*)d_in[2];
    float* out = (float*)d_out;

    pack_mask_bits_kernel<<<1024, 256>>>(mask);

    const int dyn_smem = 2 * BUF_WORDS * 4;   // 71,680 B per CTA
    static int attr_set = 0;
    if (!attr_set) {
        cudaFuncSetAttribute(attn_flash_kernel,
                             cudaFuncAttributeMaxDynamicSharedMemorySize, dyn_smem);
        attr_set = 1;
    }
    dim3 grid(T_DIM / BT, 8 * 16);
    attn_flash_kernel<<<grid, 128, dyn_smem>>>(qkv, bias, out);
}